// round 1
// baseline (speedup 1.0000x reference)
#include <cuda_runtime.h>
#include <cuda_bf16.h>

#define NN 131072      // nodes
#define NE 2097152     // edges
#define F_IN 32
#define HID 64
#define G_FEAT 16
#define NG 1024        // graphs
#define BN_EPS 1e-5f

// ---------------- scratch (static device allocations; no cudaMalloc allowed) ----
__device__ float g_dinv[NN];                 // deg -> dinv_sqrt
__device__ float g_xw[NN * HID];             // X@W result (per layer)
__device__ float g_agg[NN * HID];            // scatter accumulator / conv output
__device__ float g_sum1[HID], g_ss1[HID];
__device__ float g_sum2[HID], g_ss2[HID];
__device__ float g_scale1[HID], g_shift1[HID];
__device__ float g_scale2[HID], g_shift2[HID];
__device__ float g_pool[NG * HID];
__device__ float g_cnt[NG];

// ---------------- helpers -----------------------------------------------------
__device__ __forceinline__ void red_add_v4(float* addr, float4 v) {
    asm volatile("red.global.add.v4.f32 [%0], {%1, %2, %3, %4};"
                 :: "l"(addr), "f"(v.x), "f"(v.y), "f"(v.z), "f"(v.w)
                 : "memory");
}

// ---------------- kernels ------------------------------------------------------

// dinv[i] = 1.0 (self-loop contribution to degree)
__global__ void k_fill_ones() {
    int i = blockIdx.x * blockDim.x + threadIdx.x;
    if (i < NN) g_dinv[i] = 1.0f;
}

// deg[dst] += 1 per edge
__global__ void k_degree(const int* __restrict__ dst) {
    int e = blockIdx.x * blockDim.x + threadIdx.x;
    if (e < NE) atomicAdd(&g_dinv[dst[e]], 1.0f);
}

// dinv = rsqrt(deg)
__global__ void k_rsqrt() {
    int i = blockIdx.x * blockDim.x + threadIdx.x;
    if (i < NN) g_dinv[i] = rsqrtf(g_dinv[i]);
}

// xw = x @ W1   ([NN,32] @ [32,64])
__global__ void k_gemm1(const float* __restrict__ x, const float* __restrict__ W) {
    __shared__ float Ws[F_IN * HID];
    for (int i = threadIdx.x; i < F_IN * HID; i += blockDim.x) Ws[i] = W[i];
    __syncthreads();
    int node = blockIdx.x * blockDim.x + threadIdx.x;
    if (node >= NN) return;

    float xr[F_IN];
    const float4* xp = (const float4*)(x + (size_t)node * F_IN);
#pragma unroll
    for (int k = 0; k < F_IN / 4; k++) {
        float4 v = xp[k];
        xr[4 * k + 0] = v.x; xr[4 * k + 1] = v.y;
        xr[4 * k + 2] = v.z; xr[4 * k + 3] = v.w;
    }
    float4* op = (float4*)(g_xw + (size_t)node * HID);
    for (int j4 = 0; j4 < HID / 4; j4++) {
        float4 acc = make_float4(0.f, 0.f, 0.f, 0.f);
#pragma unroll
        for (int k = 0; k < F_IN; k++) {
            float xv = xr[k];
            const float* w = &Ws[k * HID + 4 * j4];
            acc.x += xv * w[0]; acc.y += xv * w[1];
            acc.z += xv * w[2]; acc.w += xv * w[3];
        }
        op[j4] = acc;
    }
}

// scatter: agg[dst] += xw[src] * dinv[src]*dinv[dst]   (16 threads per edge, v4 red)
__global__ void k_scatter(const int* __restrict__ src, const int* __restrict__ dst) {
    unsigned t = blockIdx.x * blockDim.x + threadIdx.x;
    unsigned e = t >> 4;
    if (e >= NE) return;
    unsigned j = t & 15u;
    int s = src[e];
    int d = dst[e];
    float norm = g_dinv[s] * g_dinv[d];
    float4 v = ((const float4*)g_xw)[(size_t)s * 16 + j];
    v.x *= norm; v.y *= norm; v.z *= norm; v.w *= norm;
    red_add_v4(&g_agg[(size_t)d * HID + 4 * j], v);
}

// v = agg + xw*dinv^2 + b ; store back to g_agg ; accumulate BN sums
__global__ void k_finalize(const float* __restrict__ bias,
                           float* __restrict__ gsum, float* __restrict__ gss) {
    int tx = threadIdx.x;   // 0..15 feature float4 group
    int ty = threadIdx.y;   // 0..15 node sub-stride
    float4 b4 = ((const float4*)bias)[tx];
    float4 ls = make_float4(0.f, 0.f, 0.f, 0.f);
    float4 lq = make_float4(0.f, 0.f, 0.f, 0.f);
    for (int i = blockIdx.x * 16 + ty; i < NN; i += gridDim.x * 16) {
        float di = g_dinv[i];
        float sw = di * di;
        float4 a = ((const float4*)g_agg)[(size_t)i * 16 + tx];
        float4 w = ((const float4*)g_xw)[(size_t)i * 16 + tx];
        float4 v;
        v.x = a.x + w.x * sw + b4.x;
        v.y = a.y + w.y * sw + b4.y;
        v.z = a.z + w.z * sw + b4.z;
        v.w = a.w + w.w * sw + b4.w;
        ((float4*)g_agg)[(size_t)i * 16 + tx] = v;
        ls.x += v.x; ls.y += v.y; ls.z += v.z; ls.w += v.w;
        lq.x += v.x * v.x; lq.y += v.y * v.y; lq.z += v.z * v.z; lq.w += v.w * v.w;
    }
    atomicAdd(&gsum[4 * tx + 0], ls.x);
    atomicAdd(&gsum[4 * tx + 1], ls.y);
    atomicAdd(&gsum[4 * tx + 2], ls.z);
    atomicAdd(&gsum[4 * tx + 3], ls.w);
    atomicAdd(&gss[4 * tx + 0], lq.x);
    atomicAdd(&gss[4 * tx + 1], lq.y);
    atomicAdd(&gss[4 * tx + 2], lq.z);
    atomicAdd(&gss[4 * tx + 3], lq.w);
}

// BN params -> scale/shift  (single block, HID threads)
__global__ void k_bnstats(const float* __restrict__ gsum, const float* __restrict__ gss,
                          const float* __restrict__ gamma, const float* __restrict__ beta,
                          float* __restrict__ scale, float* __restrict__ shift) {
    int f = threadIdx.x;
    if (f >= HID) return;
    const float invN = 1.0f / (float)NN;
    float mu = gsum[f] * invN;
    float var = gss[f] * invN - mu * mu;
    float sc = gamma[f] * rsqrtf(var + BN_EPS);
    scale[f] = sc;
    shift[f] = beta[f] - mu * sc;
}

// h = relu(BN1(v1)) fused ; xw2 = h @ W2  ([NN,64] @ [64,64])
__global__ void k_gemm2(const float* __restrict__ W) {
    __shared__ float Ws[HID * HID];
    __shared__ float sc[HID], sh[HID];
    for (int i = threadIdx.x; i < HID * HID; i += blockDim.x) Ws[i] = W[i];
    if (threadIdx.x < HID) {
        sc[threadIdx.x] = g_scale1[threadIdx.x];
        sh[threadIdx.x] = g_shift1[threadIdx.x];
    }
    __syncthreads();
    int node = blockIdx.x * blockDim.x + threadIdx.x;
    if (node >= NN) return;

    float h[HID];
#pragma unroll
    for (int k4 = 0; k4 < HID / 4; k4++) {
        float4 v = ((const float4*)g_agg)[(size_t)node * 16 + k4];
        h[4 * k4 + 0] = fmaxf(v.x * sc[4 * k4 + 0] + sh[4 * k4 + 0], 0.f);
        h[4 * k4 + 1] = fmaxf(v.y * sc[4 * k4 + 1] + sh[4 * k4 + 1], 0.f);
        h[4 * k4 + 2] = fmaxf(v.z * sc[4 * k4 + 2] + sh[4 * k4 + 2], 0.f);
        h[4 * k4 + 3] = fmaxf(v.w * sc[4 * k4 + 3] + sh[4 * k4 + 3], 0.f);
    }
    for (int j4 = 0; j4 < HID / 4; j4++) {
        float4 acc = make_float4(0.f, 0.f, 0.f, 0.f);
#pragma unroll
        for (int k = 0; k < HID; k++) {
            float hv = h[k];
            const float* w = &Ws[k * HID + 4 * j4];
            acc.x += hv * w[0]; acc.y += hv * w[1];
            acc.z += hv * w[2]; acc.w += hv * w[3];
        }
        ((float4*)g_xw)[(size_t)node * 16 + j4] = acc;
    }
}

// h2 = relu(BN2(v2)) ; pool[batch[i]] += h2 ; cnt[batch[i]] += 1
__global__ void k_pool(const int* __restrict__ batch) {
    unsigned t = blockIdx.x * blockDim.x + threadIdx.x;
    unsigned i = t >> 4;
    if (i >= NN) return;
    unsigned j = t & 15u;
    int g = batch[i];
    float4 v = ((const float4*)g_agg)[(size_t)i * 16 + j];
    float4 s4 = ((const float4*)g_scale2)[j];
    float4 h4 = ((const float4*)g_shift2)[j];
    float4 hh;
    hh.x = fmaxf(v.x * s4.x + h4.x, 0.f);
    hh.y = fmaxf(v.y * s4.y + h4.y, 0.f);
    hh.z = fmaxf(v.z * s4.z + h4.z, 0.f);
    hh.w = fmaxf(v.w * s4.w + h4.w, 0.f);
    red_add_v4(&g_pool[(size_t)g * HID + 4 * j], hh);
    if (j == 0) atomicAdd(&g_cnt[g], 1.0f);
}

// heads: one warp per graph; combined = [pooled/cnt (64), global (16)]
__global__ void k_head(const float* __restrict__ gf,
                       const float* __restrict__ Wo1, const float* __restrict__ bo1,
                       const float* __restrict__ Wo2, const float* __restrict__ bo2,
                       const float* __restrict__ Wb1, const float* __restrict__ bb1,
                       const float* __restrict__ Wb2, const float* __restrict__ bb2,
                       float* __restrict__ out) {
    int g = blockIdx.x;
    int lane = threadIdx.x;   // 0..31
    __shared__ float c[HID + G_FEAT];
    float inv = 1.0f / fmaxf(g_cnt[g], 1.0f);
    for (int k = lane; k < HID; k += 32) c[k] = g_pool[(size_t)g * HID + k] * inv;
    if (lane < G_FEAT) c[HID + lane] = gf[(size_t)g * G_FEAT + lane];
    __syncwarp();

    // orange head
    float ho = bo1[lane];
#pragma unroll 8
    for (int k = 0; k < HID + G_FEAT; k++) ho += c[k] * Wo1[k * 32 + lane];
    ho = fmaxf(ho, 0.f) * Wo2[lane];
#pragma unroll
    for (int o = 16; o; o >>= 1) ho += __shfl_xor_sync(0xffffffffu, ho, o);
    if (lane == 0) out[g] = ho + bo2[0];

    // blue head
    float hb = bb1[lane];
#pragma unroll 8
    for (int k = 0; k < HID + G_FEAT; k++) hb += c[k] * Wb1[k * 32 + lane];
    hb = fmaxf(hb, 0.f) * Wb2[lane];
#pragma unroll
    for (int o = 16; o; o >>= 1) hb += __shfl_xor_sync(0xffffffffu, hb, o);
    if (lane == 0) out[NG + g] = hb + bb2[0];
}

// ---------------- launch --------------------------------------------------------
extern "C" void kernel_launch(void* const* d_in, const int* in_sizes, int n_in,
                              void* d_out, int out_size) {
    const float* x      = (const float*)d_in[0];
    const int*   ei     = (const int*)d_in[1];
    const int*   batch  = (const int*)d_in[2];
    const float* gf     = (const float*)d_in[3];
    const float* W1     = (const float*)d_in[4];
    const float* b1     = (const float*)d_in[5];
    const float* gamma1 = (const float*)d_in[6];
    const float* beta1  = (const float*)d_in[7];
    const float* W2     = (const float*)d_in[8];
    const float* b2     = (const float*)d_in[9];
    const float* gamma2 = (const float*)d_in[10];
    const float* beta2  = (const float*)d_in[11];
    const float* Wo1    = (const float*)d_in[12];
    const float* bo1    = (const float*)d_in[13];
    const float* Wo2    = (const float*)d_in[14];
    const float* bo2    = (const float*)d_in[15];
    const float* Wb1    = (const float*)d_in[16];
    const float* bb1    = (const float*)d_in[17];
    const float* Wb2    = (const float*)d_in[18];
    const float* bb2    = (const float*)d_in[19];
    float* out = (float*)d_out;

    const int* src = ei;
    const int* dst = ei + NE;

    void *p_agg, *p_sum1, *p_ss1, *p_sum2, *p_ss2, *p_pool, *p_cnt;
    void *p_scale1, *p_shift1, *p_scale2, *p_shift2;
    cudaGetSymbolAddress(&p_agg,   g_agg);
    cudaGetSymbolAddress(&p_sum1,  g_sum1);
    cudaGetSymbolAddress(&p_ss1,   g_ss1);
    cudaGetSymbolAddress(&p_sum2,  g_sum2);
    cudaGetSymbolAddress(&p_ss2,   g_ss2);
    cudaGetSymbolAddress(&p_pool,  g_pool);
    cudaGetSymbolAddress(&p_cnt,   g_cnt);
    cudaGetSymbolAddress(&p_scale1, g_scale1);
    cudaGetSymbolAddress(&p_shift1, g_shift1);
    cudaGetSymbolAddress(&p_scale2, g_scale2);
    cudaGetSymbolAddress(&p_shift2, g_shift2);

    // zero accumulators
    cudaMemsetAsync(p_agg,  0, sizeof(float) * NN * HID);
    cudaMemsetAsync(p_sum1, 0, sizeof(float) * HID);
    cudaMemsetAsync(p_ss1,  0, sizeof(float) * HID);
    cudaMemsetAsync(p_sum2, 0, sizeof(float) * HID);
    cudaMemsetAsync(p_ss2,  0, sizeof(float) * HID);
    cudaMemsetAsync(p_pool, 0, sizeof(float) * NG * HID);
    cudaMemsetAsync(p_cnt,  0, sizeof(float) * NG);

    // degree / dinv
    k_fill_ones<<<NN / 256, 256>>>();
    k_degree<<<NE / 256, 256>>>(dst);
    k_rsqrt<<<NN / 256, 256>>>();

    // ----- layer 1 -----
    k_gemm1<<<NN / 128, 128>>>(x, W1);
    k_scatter<<<(NE * 16) / 256, 256>>>(src, dst);
    k_finalize<<<512, dim3(16, 16)>>>(b1, (float*)p_sum1, (float*)p_ss1);
    k_bnstats<<<1, HID>>>((const float*)p_sum1, (const float*)p_ss1, gamma1, beta1,
                          (float*)p_scale1, (float*)p_shift1);

    // ----- layer 2 -----
    k_gemm2<<<NN / 128, 128>>>(W2);                     // reads g_agg(v1)+BN1, writes g_xw
    cudaMemsetAsync(p_agg, 0, sizeof(float) * NN * HID); // after gemm2 in stream order
    k_scatter<<<(NE * 16) / 256, 256>>>(src, dst);
    k_finalize<<<512, dim3(16, 16)>>>(b2, (float*)p_sum2, (float*)p_ss2);
    k_bnstats<<<1, HID>>>((const float*)p_sum2, (const float*)p_ss2, gamma2, beta2,
                          (float*)p_scale2, (float*)p_shift2);

    // ----- pool + heads -----
    k_pool<<<(NN * 16) / 256, 256>>>(batch);
    k_head<<<NG, 32>>>(gf, Wo1, bo1, Wo2, bo2, Wb1, bb1, Wb2, bb2, out);
}